// round 4
// baseline (speedup 1.0000x reference)
#include <cuda_runtime.h>

// CRF NLL, exp-domain forward scan. One WARP per batch (no CTA barriers).
// B=512, S=512, T=64. Thread lane owns tags {2*lane, 2*lane+1}.
// q_s[to] = (sum_from q_{s-1}[from] * E[from,to]) * exp(f_s[to]) / q_{s-1}[0]
// C_s = C_{s-1} + log(q_{s-1}[0]);  part_s = log(q_s) + C_s.

constexpr int Bb = 512;
constexpr int Ss = 512;
constexpr int Tt = 64;
constexpr int START = Tt - 2;
constexpr int STOP  = Tt - 1;
constexpr int PD    = 4;      // feats prefetch depth (steps)

__device__ float g_partial[Bb];
__device__ unsigned int g_count = 0;

typedef unsigned long long u64;

static __device__ __forceinline__ u64 fma2(u64 a, u64 b, u64 c) {
    u64 d;
    asm("fma.rn.f32x2 %0, %1, %2, %3;" : "=l"(d) : "l"(a), "l"(b), "l"(c));
    return d;
}
static __device__ __forceinline__ u64 add2(u64 a, u64 b) {
    u64 d;
    asm("add.rn.f32x2 %0, %1, %2;" : "=l"(d) : "l"(a), "l"(b));
    return d;
}
static __device__ __forceinline__ u64 pack2(float lo, float hi) {
    u64 d;
    asm("mov.b64 %0, {%1, %2};" : "=l"(d) : "f"(lo), "f"(hi));
    return d;
}
static __device__ __forceinline__ void unpack2(u64 v, float& lo, float& hi) {
    asm("mov.b64 {%0, %1}, %2;" : "=f"(lo), "=f"(hi) : "l"(v));
}
static __device__ __forceinline__ float rcp_approx(float x) {
    float r;
    asm("rcp.approx.f32 %0, %1;" : "=f"(r) : "f"(x));
    return r;
}
static __device__ __forceinline__ float warp_sum(float v) {
    #pragma unroll
    for (int off = 16; off > 0; off >>= 1)
        v += __shfl_xor_sync(0xffffffffu, v, off);
    return v;
}

__global__ __launch_bounds__(32) void crf_kernel(
    const float* __restrict__ feats,
    const unsigned char* __restrict__ mask8,
    const int* __restrict__ tags,
    const float* __restrict__ trans,
    float* __restrict__ out)
{
    const int b    = blockIdx.x;
    const int lane = threadIdx.x;         // 0..31
    const int to0  = 2 * lane;            // owned tags: to0, to0+1

    __shared__ __align__(16) float qbuf[2][Tt];   // q in exp domain, double-buffered

    // ---- mask layout probe (uint8 vs int32) + sequence length ----
    const int* mask32 = reinterpret_cast<const int*>(mask8);
    const bool is32 = (mask8[0] == 1 && mask8[1] == 0 && mask8[2] == 0 && mask8[3] == 0);

    int cnt = 0;
    #pragma unroll
    for (int k = 0; k < Ss / 32; ++k) {
        int s  = lane + k * 32;
        int mv = is32 ? mask32[b * Ss + s] : (int)mask8[b * Ss + s];
        cnt += (mv != 0);
    }
    #pragma unroll
    for (int off = 16; off > 0; off >>= 1)
        cnt += __shfl_xor_sync(0xffffffffu, cnt, off);
    const int L = cnt;                     // >= S/2 = 256

    const float* fb = feats + (size_t)b * Ss * Tt;
    const int*   tg = tags + b * Ss;

    // ---- gold path score ----
    float gsum = 0.f;
    for (int s = lane; s < L; s += 32) {
        int t1 = tg[s];
        int t0 = (s == 0) ? START : tg[s - 1];
        gsum += fb[s * Tt + t1] + trans[t0 * Tt + t1];
    }
    float gold = warp_sum(gsum) + trans[tg[L - 1] * Tt + STOP];

    // ---- E pairs packed along FROM: E2x[k] = (exp(tr[2k][tox]), exp(tr[2k+1][tox])) ----
    u64 E2a[Tt / 2], E2b[Tt / 2];
    #pragma unroll
    for (int k = 0; k < Tt / 2; ++k) {
        E2a[k] = pack2(__expf(trans[(2 * k) * Tt + to0]),
                       __expf(trans[(2 * k + 1) * Tt + to0]));
        E2b[k] = pack2(__expf(trans[(2 * k) * Tt + to0 + 1]),
                       __expf(trans[(2 * k + 1) * Tt + to0 + 1]));
    }

    // ---- init: part_0 = f_0 + trans[START,:]; q_0 = exp(part_0 - part_0[0]) ----
    const float c0 = fb[0] + trans[START * Tt];   // broadcast loads
    float logC = c0;
    {
        float2 f0 = *reinterpret_cast<const float2*>(fb + to0);
        float2 q0;
        q0.x = __expf(f0.x + trans[START * Tt + to0]     - c0);
        q0.y = __expf(f0.y + trans[START * Tt + to0 + 1] - c0);
        *reinterpret_cast<float2*>(&qbuf[0][to0]) = q0;
    }

    // ---- feats pipeline: exp(f) computed at prefetch time (off critical path) ----
    float efa[PD], efb[PD];
    #pragma unroll
    for (int r = 0; r < PD; ++r) {
        float2 f = *reinterpret_cast<const float2*>(fb + (1 + r) * Tt + to0);
        efa[r] = __expf(f.x);
        efb[r] = __expf(f.y);
    }

    float cur0 = 0.f, cur1 = 0.f;

    auto step = [&](int s, float ea, float eb) {
        __syncwarp();
        const ulonglong2* qp = reinterpret_cast<const ulonglong2*>(qbuf[(s - 1) & 1]);

        ulonglong2 w = qp[0];
        float q0, qd;
        unpack2(w.x, q0, qd);
        const float r  = rcp_approx(q0);      // overlaps FMA loop
        logC += __logf(q0);                   // independent side chain

        u64 a0 = fma2(w.x, E2a[0], 0ull);
        u64 a1 = fma2(w.y, E2a[1], 0ull);
        u64 b0 = fma2(w.x, E2b[0], 0ull);
        u64 b1 = fma2(w.y, E2b[1], 0ull);
        #pragma unroll
        for (int j = 1; j < 16; ++j) {
            w = qp[j];
            a0 = fma2(w.x, E2a[2 * j],     a0);
            a1 = fma2(w.y, E2a[2 * j + 1], a1);
            b0 = fma2(w.x, E2b[2 * j],     b0);
            b1 = fma2(w.y, E2b[2 * j + 1], b1);
        }
        float alo, ahi, blo, bhi;
        unpack2(add2(a0, a1), alo, ahi);
        unpack2(add2(b0, b1), blo, bhi);
        cur0 = (alo + ahi) * (ea * r);
        cur1 = (blo + bhi) * (eb * r);
        *reinterpret_cast<float2*>(&qbuf[s & 1][to0]) = make_float2(cur0, cur1);
    };

    // ---- forward scan, unrolled x PD with deep prefetch ----
    int s = 1;
    for (; s + (PD - 1) < L; ) {
        #pragma unroll
        for (int r = 0; r < PD; ++r) {
            const float ea = efa[r], eb = efb[r];
            if (s + PD < L) {
                float2 f = *reinterpret_cast<const float2*>(fb + (s + PD) * Tt + to0);
                efa[r] = __expf(f.x);
                efb[r] = __expf(f.y);
            }
            step(s, ea, eb);
            ++s;
        }
    }
    for (; s < L; ++s) {
        int r = (s - 1) & (PD - 1);
        step(s, efa[r], efb[r]);
    }

    // ---- final transition to STOP ----
    float fin = cur0 * __expf(trans[to0 * Tt + STOP])
              + cur1 * __expf(trans[(to0 + 1) * Tt + STOP]);
    fin = warp_sum(fin);
    const float nll = (logC + __logf(fin)) - gold;

    __shared__ bool is_last;
    if (lane == 0) {
        g_partial[b] = nll;
        __threadfence();
        unsigned int c = atomicAdd(&g_count, 1u);
        is_last = (c == (unsigned)gridDim.x - 1);
    }
    __syncwarp();

    // ---- last block: deterministic reduction over batches ----
    if (is_last) {
        __threadfence();
        float sum = 0.f;
        #pragma unroll
        for (int k = 0; k < Bb / 32; ++k) {
            float v;
            asm volatile("ld.global.cg.f32 %0, [%1];" : "=f"(v)
                         : "l"(&g_partial[lane + k * 32]));
            sum += v;
        }
        sum = warp_sum(sum);
        if (lane == 0) {
            out[0] = sum;
            g_count = 0;   // reset for next (graph-replayed) launch
        }
    }
}

extern "C" void kernel_launch(void* const* d_in, const int* in_sizes, int n_in,
                              void* d_out, int out_size)
{
    (void)in_sizes; (void)n_in; (void)out_size;
    const float*         feats = (const float*)d_in[0];
    const unsigned char* mask  = (const unsigned char*)d_in[1];
    const int*           tags  = (const int*)d_in[2];
    const float*         trans = (const float*)d_in[3];

    crf_kernel<<<Bb, 32>>>(feats, mask, tags, trans, (float*)d_out);
}